// round 10
// baseline (speedup 1.0000x reference)
#include <cuda_runtime.h>
#include <cuda_fp16.h>
#include <math.h>
#include <stdint.h>

// ============================================================
// mma.sync (HMMA) fp16-split GEMM chain for the 6-layer MLP.
// fp32 x fp32 emulated as (hi+lo fp16): hh + hl + lh, fp32 accum.
// R10: manually software-pipelined mainloop — every LDSM batch
//      is covered by a 16-MMA block; tensor pipe never waits on
//      shared memory in steady state.
// ============================================================

#define BATCH 65536
#define XDIM 512

// Blocked tile: [tile][chunk 0..15][plane hi/lo][128 rows x 64 B], pre-swizzled.
#define PLANE_B   8192
#define CHUNK_B   16384
#define TILE_B    262144

// ---------- scratch (no cudaMalloc allowed) ----------
__device__ __align__(256) char g_ablk0[(size_t)512 * TILE_B];
__device__ __align__(256) char g_ablk1[(size_t)512 * TILE_B];
__device__ __align__(256) char g_wblk[(size_t)21 * TILE_B];

// ---------- PTX helpers ----------
__device__ __forceinline__ uint32_t smem_u32(const void* p) {
    uint32_t a;
    asm("{ .reg .u64 t; cvta.to.shared.u64 t, %1; cvt.u32.u64 %0, t; }" : "=r"(a) : "l"(p));
    return a;
}
#define MBARRIER_INIT(addr, cnt) \
    asm volatile("mbarrier.init.shared.b64 [%0], %1;" :: "r"(addr), "r"(cnt) : "memory")
#define MBARRIER_EXPECT_TX(addr, bytes) \
    asm volatile("mbarrier.arrive.expect_tx.shared.b64 _, [%0], %1;" :: "r"(addr), "r"(bytes) : "memory")
#define MBARRIER_ARRIVE(addr) \
    asm volatile("mbarrier.arrive.release.cta.shared.b64 _, [%0];" :: "r"(addr) : "memory")
#define MBARRIER_WAIT_PARITY(addr, parity) do {                                      \
    uint32_t _m = (addr); uint32_t _p = (parity); uint32_t _d;                        \
    asm volatile("{\n\t.reg .pred p;\n\t"                                             \
        "mbarrier.try_wait.parity.acquire.cta.shared::cta.b64 p, [%1], %2;\n\t"       \
        "selp.b32 %0, 1, 0, p;\n\t}" : "=r"(_d) : "r"(_m), "r"(_p) : "memory");       \
    if (!_d) {                                                                        \
        asm volatile("{\n\t.reg .pred P1;\n\t"                                        \
            "W_%=:\n\t"                                                               \
            "mbarrier.try_wait.parity.acquire.cta.shared::cta.b64 P1, [%0], %1, 0x989680;\n\t" \
            "@P1 bra.uni D_%=;\n\t"                                                   \
            "bra.uni W_%=;\n\t"                                                       \
            "D_%=:\n\t}" :: "r"(_m), "r"(_p) : "memory");                             \
    }                                                                                 \
} while (0)
#define CP_BULK(dst, src, bytes, bar)                                                 \
    asm volatile("cp.async.bulk.shared::cluster.global.mbarrier::complete_tx::bytes " \
                 "[%0], [%1], %2, [%3];"                                              \
                 :: "r"(dst), "l"(src), "r"(bytes), "r"(bar) : "memory")
#define FENCE_ASYNC_SHARED() asm volatile("fence.proxy.async.shared::cta;" ::: "memory")

__device__ __forceinline__ void ldsm4(uint32_t r[4], uint32_t addr) {
    asm volatile("ldmatrix.sync.aligned.m8n8.x4.shared.b16 {%0,%1,%2,%3}, [%4];"
                 : "=r"(r[0]), "=r"(r[1]), "=r"(r[2]), "=r"(r[3]) : "r"(addr));
}
__device__ __forceinline__ void mma16816(float c[4], const uint32_t a[4], const uint32_t* b) {
    asm volatile(
        "mma.sync.aligned.m16n8k16.row.col.f32.f16.f16.f32 "
        "{%0,%1,%2,%3}, {%4,%5,%6,%7}, {%8,%9}, {%0,%1,%2,%3};"
        : "+f"(c[0]), "+f"(c[1]), "+f"(c[2]), "+f"(c[3])
        : "r"(a[0]), "r"(a[1]), "r"(a[2]), "r"(a[3]), "r"(b[0]), "r"(b[1]));
}

// one 16-MMA block: 4 m-tiles x 4 n8-tiles (all independent accumulators)
__device__ __forceinline__ void mma_block(float acc[4][4][4], const uint32_t a[4][4],
                                          const uint32_t b0[4], const uint32_t b1[4]) {
#pragma unroll
    for (int ni = 0; ni < 4; ni++) {
        const uint32_t* bp = (ni < 2) ? (b0 + (ni & 1) * 2) : (b1 + (ni & 1) * 2);
#pragma unroll
        for (int mi = 0; mi < 4; mi++) mma16816(acc[mi][ni], a[mi], bp);
    }
}

// ---------- activation ----------
__device__ __forceinline__ float act_clip(float h, int f, float mx) {
    float o;
    if (f == 0) {
        o = fmaxf(h, 0.0f);
    } else if (f == 1) {
        o = 1.0f / (1.0f + expf(-h));
    } else if (f == 2) {
        o = tanhf(h);
    } else if (f == 3) {
        o = (h > 0.0f) ? h : 0.1f * h;
    } else {
        const float lam = 1.0507009873554805f;
        const float alp = 1.6732632423543772f;
        o = (h > 0.0f) ? lam * h : lam * alp * expm1f(h);
    }
    return fminf(o, mx);
}

__device__ __forceinline__ uint32_t pack_h2(float x0, float x1) {
    __half2 h = __floats2half2_rn(x0, x1);
    return *(uint32_t*)&h;
}

__device__ __forceinline__ uint32_t blk_off(int r, int q) {
    return (uint32_t)(r * 64 + ((q * 16) ^ ((r & 6) << 3)));
}

// ---------- merged split: fp32 -> blocked hi/lo fp16 ----------
__global__ __launch_bounds__(256)
void split_all_kernel(const float* __restrict__ input,
                      const float* __restrict__ W_in,
                      const float* __restrict__ W_h,
                      const float* __restrict__ W_out,
                      char* __restrict__ ablk, char* __restrict__ wblk)
{
    int idx = blockIdx.x * 256 + threadIdx.x;
    const float* src;
    char* dst;
    int row;
    if (idx < BATCH * 64) {
        src = input; dst = ablk; row = idx >> 6;
    } else if (idx < (BATCH + 512) * 64) {
        idx -= BATCH * 64;
        src = W_in; dst = wblk; row = idx >> 6;
    } else if (idx < (BATCH + 512 + 2048) * 64) {
        idx -= (BATCH + 512) * 64;
        src = W_h; dst = wblk + (size_t)4 * TILE_B; row = idx >> 6;
    } else if (idx < (BATCH + 512 + 2048 + 128) * 64) {
        idx -= (BATCH + 512 + 2048) * 64;
        src = W_out; dst = wblk + (size_t)20 * TILE_B; row = idx >> 6;
    } else {
        return;
    }
    const int h8 = idx & 63;
    const int k0 = h8 * 8;
    const int c  = k0 >> 5;
    const int q  = (k0 >> 3) & 3;
    const int t  = row >> 7;
    const int r  = row & 127;

    float4 a = *(const float4*)(src + (size_t)row * 512 + k0);
    float4 b = *(const float4*)(src + (size_t)row * 512 + k0 + 4);
    float x[8] = {a.x, a.y, a.z, a.w, b.x, b.y, b.z, b.w};
    uint32_t hw[4], lw[4];
#pragma unroll
    for (int i = 0; i < 4; i++) {
        float h0 = __half2float(__float2half_rn(x[2 * i]));
        float h1 = __half2float(__float2half_rn(x[2 * i + 1]));
        hw[i] = pack_h2(x[2 * i], x[2 * i + 1]);
        lw[i] = pack_h2(x[2 * i] - h0, x[2 * i + 1] - h1);
    }
    char* base = dst + (size_t)t * TILE_B + (size_t)c * CHUNK_B;
    const uint32_t off = blk_off(r, q);
    *(uint4*)(base + off)           = make_uint4(hw[0], hw[1], hw[2], hw[3]);
    *(uint4*)(base + PLANE_B + off) = make_uint4(lw[0], lw[1], lw[2], lw[3]);
}

// ============================================================
// C[128,128] tile of act(A @ W^T + b). K = 512 (16 chunks, 32 k16 steps).
// 8 warps 2(M)x4(N), warp 64x32. 3-stage cp.async.bulk ring.
// Software-pipelined: lh(prev) covers ah/bh loads, hh covers bl,
// hl covers al. Fully unrolled (all stage ids / parities literal).
// ============================================================
template<bool OUT_FP32>
__global__ __launch_bounds__(256, 2)
void bnn_gemm_kernel(const char* __restrict__ Ablk,
                     const char* __restrict__ Wblk,
                     const float* __restrict__ bias,
                     const int* __restrict__ fid,
                     const float* __restrict__ mcap,
                     float* __restrict__ OutF,
                     char* __restrict__ Oblk)
{
    extern __shared__ char smem[];
    constexpr int NCHUNK = 16;
    constexpr int NSTEP  = 32;        // 2 k16 steps per chunk
    constexpr int STAGE  = 32768;
    constexpr int AL_OFF = 8192;
    constexpr int BH_OFF = 16384;
    constexpr int BL_OFF = 24576;

    const int tid  = threadIdx.x;
    const int lane = tid & 31;
    const int wid  = tid >> 5;
    const int mtile = blockIdx.y;
    const int ntile = blockIdx.x;
    const uint32_t sb     = smem_u32(smem);
    const uint32_t s_full = sb;            // 3 full barriers  @ 0, 8, 16
    const uint32_t s_empt = sb + 24;       // 3 empty barriers @ 24, 32, 40
    const uint32_t s_stg  = sb + 128;

    const int mw = (wid & 1) * 64;
    const int nw = (wid >> 1) * 32;

    const int lA_r = (lane & 7) + ((lane >> 3) & 1) * 8;
    const int lA_c = (lane >> 4) & 1;
    const int lB_r = (lane & 7) + ((lane >> 4) & 1) * 8;
    const int lB_c = (lane >> 3) & 1;

    const uint32_t swzA = (uint32_t)((lA_r & 6) << 3);
    const uint32_t swzB = (uint32_t)((lB_r & 6) << 3);
    uint32_t rowA[4], rowB[2];
#pragma unroll
    for (int mi = 0; mi < 4; mi++) rowA[mi] = (uint32_t)((mw + mi * 16 + lA_r) * 64);
#pragma unroll
    for (int t = 0; t < 2; t++)    rowB[t]  = (uint32_t)((nw + t * 16 + lB_r) * 64);

    float acc[4][4][4];
#pragma unroll
    for (int i = 0; i < 4; i++)
#pragma unroll
        for (int j = 0; j < 4; j++)
#pragma unroll
            for (int v = 0; v < 4; v++) acc[i][j][v] = 0.0f;

    const char* Asrc = Ablk + (size_t)mtile * TILE_B;
    const char* Wsrc = Wblk + (size_t)ntile * TILE_B;

    // ---- init barriers + prologue bulk loads (chunks 0,1,2) ----
    if (tid == 0) {
#pragma unroll
        for (int s = 0; s < 3; s++) {
            MBARRIER_INIT(s_full + s * 8, 1);
            MBARRIER_INIT(s_empt + s * 8, 8);      // one arrive per warp
        }
    }
    FENCE_ASYNC_SHARED();
    __syncthreads();
    if (tid == 0) {
#pragma unroll
        for (int s = 0; s < 3; s++) {
            const uint32_t bar = s_full + s * 8;
            const uint32_t stg = s_stg + s * STAGE;
            MBARRIER_EXPECT_TX(bar, 32768);
            CP_BULK(stg,          Asrc + (size_t)s * CHUNK_B, 16384, bar);
            CP_BULK(stg + BH_OFF, Wsrc + (size_t)s * CHUNK_B, 16384, bar);
        }
    }

    // ---- fragment registers ----
    uint32_t ah[4][4];          // current A-hi (single buffer)
    uint32_t al[2][4][4];       // A-lo, parity-buffered (used by next step's lh)
    uint32_t bh[2][2][4];       // B-hi, parity-buffered
    uint32_t bl[2][4];          // B-lo, current

    // ---- pipeline prologue: wait chunk 0, load ah/bh for step 0 ----
    MBARRIER_WAIT_PARITY(s_full + 0, 0);
    {
        const uint32_t stg = s_stg;
        const uint32_t swA = (uint32_t)(lA_c * 16) ^ swzA;
        const uint32_t swB = (uint32_t)(lB_c * 16) ^ swzB;
#pragma unroll
        for (int mi = 0; mi < 4; mi++) ldsm4(ah[mi], stg + rowA[mi] + swA);
        ldsm4(bh[0][0], stg + BH_OFF + rowB[0] + swB);
        ldsm4(bh[0][1], stg + BH_OFF + rowB[1] + swB);
    }

#pragma unroll
    for (int t = 0; t < NSTEP; t++) {
        const int c  = t >> 1;             // chunk
        const int ks = t & 1;              // k16 half within chunk
        const int s  = c % 3;              // stage (compile-time)
        const int p  = t & 1;              // buffer parity
        const uint32_t stg = s_stg + s * STAGE;
        const uint32_t swA = (uint32_t)((ks * 2 + lA_c) * 16) ^ swzA;
        const uint32_t swB = (uint32_t)((ks * 2 + lB_c) * 16) ^ swzB;

        // (1) lh of PREVIOUS step — covers the ah/bh loads issued at the
        //     end of the previous iteration (registers only).
        if (t > 0) {
            const int q = (t - 1) & 1;
            mma_block(acc, al[q], bh[q][0], bh[q][1]);
        }

        // (2) load B-lo for this step
        ldsm4(bl[0], stg + BL_OFF + rowB[0] + swB);
        ldsm4(bl[1], stg + BL_OFF + rowB[1] + swB);

        // (3) hh block — covers bl latency
        mma_block(acc, ah, bh[p][0], bh[p][1]);

        // (4) load A-lo for this step; last smem read of the stage at ks==1
        #pragma unroll
        for (int mi = 0; mi < 4; mi++) ldsm4(al[p][mi], stg + AL_OFF + rowA[mi] + swA);
        if (ks == 1 && lane == 0) MBARRIER_ARRIVE(s_empt + s * 8);

        // (5) hl block — covers al latency
        mma_block(acc, ah, bl[0], bl[1]);

        // (6) load next step's ah/bh (next iteration's lh covers this)
        if (t + 1 < NSTEP) {
            const int c2  = (t + 1) >> 1;
            const int ks2 = (t + 1) & 1;
            const int s2  = c2 % 3;
            const int p2  = (t + 1) & 1;
            if (ks2 == 0) MBARRIER_WAIT_PARITY(s_full + s2 * 8, (c2 / 3) & 1);
            const uint32_t stg2 = s_stg + s2 * STAGE;
            const uint32_t swA2 = (uint32_t)((ks2 * 2 + lA_c) * 16) ^ swzA;
            const uint32_t swB2 = (uint32_t)((ks2 * 2 + lB_c) * 16) ^ swzB;
#pragma unroll
            for (int mi = 0; mi < 4; mi++) ldsm4(ah[mi], stg2 + rowA[mi] + swA2);
            ldsm4(bh[p2][0], stg2 + BH_OFF + rowB[0] + swB2);
            ldsm4(bh[p2][1], stg2 + BH_OFF + rowB[1] + swB2);
        }

        // (7) producer refill (tid 0) at end of each chunk
        if (ks == 1 && c + 3 < NCHUNK) {
            if (tid == 0) {
                MBARRIER_WAIT_PARITY(s_empt + s * 8, (c / 3) & 1);
                const uint32_t bar = s_full + s * 8;
                MBARRIER_EXPECT_TX(bar, 32768);
                CP_BULK(stg,          Asrc + (size_t)(c + 3) * CHUNK_B, 16384, bar);
                CP_BULK(stg + BH_OFF, Wsrc + (size_t)(c + 3) * CHUNK_B, 16384, bar);
            }
        }
    }
    // final lh (step 31, parity 1)
    mma_block(acc, al[1], bh[1][0], bh[1][1]);

    // ---------- epilogue ----------
    const int colq = (lane & 3) * 2;
#pragma unroll
    for (int ni = 0; ni < 4; ni++) {
        const int col = ntile * 128 + nw + ni * 8 + colq;
        const float2 b2 = *(const float2*)(bias + col);
        const int2   f2 = *(const int2*)(fid + col);
        const float2 m2 = *(const float2*)(mcap + col);
        const int oc = col >> 5;
        const int oq = (col >> 3) & 3;
        const int ob = (col & 7) * 2;
#pragma unroll
        for (int mi = 0; mi < 4; mi++) {
#pragma unroll
            for (int h = 0; h < 2; h++) {
                const int row = mtile * 128 + mw + mi * 16 + (lane >> 2) + h * 8;
                const float r0 = act_clip(acc[mi][ni][h * 2 + 0] + b2.x, f2.x, m2.x);
                const float r1 = act_clip(acc[mi][ni][h * 2 + 1] + b2.y, f2.y, m2.y);
                if (OUT_FP32) {
                    *(float2*)(OutF + (size_t)row * 128 + col) = make_float2(r0, r1);
                } else {
                    const int rr = row & 127;
                    char* base = Oblk + (size_t)(row >> 7) * TILE_B + (size_t)oc * CHUNK_B;
                    const uint32_t off = blk_off(rr, oq) + ob;
                    const float h0 = __half2float(__float2half_rn(r0));
                    const float h1 = __half2float(__float2half_rn(r1));
                    *(uint32_t*)(base + off)           = pack_h2(r0, r1);
                    *(uint32_t*)(base + PLANE_B + off) = pack_h2(r0 - h0, r1 - h1);
                }
            }
        }
    }
}

// ============================================================
extern "C" void kernel_launch(void* const* d_in, const int* in_sizes, int n_in,
                              void* d_out, int out_size)
{
    const float* input  = (const float*)d_in[0];
    const float* W_in   = (const float*)d_in[1];
    const float* b_in   = (const float*)d_in[2];
    const float* W_h    = (const float*)d_in[3];
    const float* b_h    = (const float*)d_in[4];
    const float* W_out  = (const float*)d_in[5];
    const float* b_out  = (const float*)d_in[6];
    const float* m_in   = (const float*)d_in[7];
    const float* m_h    = (const float*)d_in[8];
    const float* m_out  = (const float*)d_in[9];
    const int*   fid_in  = (const int*)d_in[10];
    const int*   fid_h   = (const int*)d_in[11];
    const int*   fid_out = (const int*)d_in[12];
    float* out = (float*)d_out;

    char *ablk0, *ablk1, *wblk;
    cudaGetSymbolAddress((void**)&ablk0, g_ablk0);
    cudaGetSymbolAddress((void**)&ablk1, g_ablk1);
    cudaGetSymbolAddress((void**)&wblk, g_wblk);

    constexpr int SMEM = 128 + 3 * 32768;   // 98432
    cudaFuncSetAttribute(bnn_gemm_kernel<false>,
                         cudaFuncAttributeMaxDynamicSharedMemorySize, SMEM);
    cudaFuncSetAttribute(bnn_gemm_kernel<true>,
                         cudaFuncAttributeMaxDynamicSharedMemorySize, SMEM);

    const int B = BATCH, X = XDIM;
    char* w_in_blk  = wblk;
    char* w_h_blk   = wblk + (size_t)4 * TILE_B;
    char* w_out_blk = wblk + (size_t)20 * TILE_B;

    const int total_slots = (B + 512 + 2048 + 128) * 64;
    split_all_kernel<<<(total_slots + 255) / 256, 256>>>(
        input, W_in, W_h, W_out, ablk0, wblk);

    dim3 blk(256);
    dim3 grid512(4, B / 128);
    dim3 grid128(1, B / 128);

    bnn_gemm_kernel<false><<<grid512, blk, SMEM>>>(
        ablk0, w_in_blk, b_in, fid_in, m_in, nullptr, ablk1);

    char *cur = ablk1, *nxt = ablk0;
    for (int i = 0; i < 4; i++) {
        bnn_gemm_kernel<false><<<grid512, blk, SMEM>>>(
            cur, w_h_blk + (size_t)i * 4 * TILE_B,
            b_h + i * X, fid_h + i * X, m_h + i * X, nullptr, nxt);
        char* t = cur; cur = nxt; nxt = t;
    }

    bnn_gemm_kernel<true><<<grid128, blk, SMEM>>>(
        cur, w_out_blk, b_out, fid_out, m_out, out, nullptr);
}

// round 11
// speedup vs baseline: 1.2511x; 1.2511x over previous
#include <cuda_runtime.h>
#include <cuda_fp16.h>
#include <math.h>
#include <stdint.h>

// ============================================================
// mma.sync (HMMA) fp16-split GEMM chain for the 6-layer MLP.
// fp32 x fp32 emulated as (hi+lo fp16): hh + hl + lh, fp32 accum.
// R11: register-lean 128x64 CTA tile, warp tile 32x32, 3 CTAs/SM
//      (24 warps/SM) — warp-count latency hiding.
// ============================================================

#define BATCH 65536
#define XDIM 512

// Blocked tile: [tile][chunk 0..15][plane hi/lo][128 rows x 64 B], pre-swizzled.
#define PLANE_B   8192
#define CHUNK_B   16384
#define TILE_B    262144

// ---------- scratch (no cudaMalloc allowed) ----------
__device__ __align__(256) char g_ablk0[(size_t)512 * TILE_B];
__device__ __align__(256) char g_ablk1[(size_t)512 * TILE_B];
__device__ __align__(256) char g_wblk[(size_t)21 * TILE_B];

// ---------- PTX helpers ----------
__device__ __forceinline__ uint32_t smem_u32(const void* p) {
    uint32_t a;
    asm("{ .reg .u64 t; cvta.to.shared.u64 t, %1; cvt.u32.u64 %0, t; }" : "=r"(a) : "l"(p));
    return a;
}
#define MBARRIER_INIT(addr, cnt) \
    asm volatile("mbarrier.init.shared.b64 [%0], %1;" :: "r"(addr), "r"(cnt) : "memory")
#define MBARRIER_EXPECT_TX(addr, bytes) \
    asm volatile("mbarrier.arrive.expect_tx.shared.b64 _, [%0], %1;" :: "r"(addr), "r"(bytes) : "memory")
#define MBARRIER_ARRIVE(addr) \
    asm volatile("mbarrier.arrive.release.cta.shared.b64 _, [%0];" :: "r"(addr) : "memory")
#define MBARRIER_WAIT_PARITY(addr, parity) do {                                      \
    uint32_t _m = (addr); uint32_t _p = (parity); uint32_t _d;                        \
    asm volatile("{\n\t.reg .pred p;\n\t"                                             \
        "mbarrier.try_wait.parity.acquire.cta.shared::cta.b64 p, [%1], %2;\n\t"       \
        "selp.b32 %0, 1, 0, p;\n\t}" : "=r"(_d) : "r"(_m), "r"(_p) : "memory");       \
    if (!_d) {                                                                        \
        asm volatile("{\n\t.reg .pred P1;\n\t"                                        \
            "W_%=:\n\t"                                                               \
            "mbarrier.try_wait.parity.acquire.cta.shared::cta.b64 P1, [%0], %1, 0x989680;\n\t" \
            "@P1 bra.uni D_%=;\n\t"                                                   \
            "bra.uni W_%=;\n\t"                                                       \
            "D_%=:\n\t}" :: "r"(_m), "r"(_p) : "memory");                             \
    }                                                                                 \
} while (0)
#define CP_BULK(dst, src, bytes, bar)                                                 \
    asm volatile("cp.async.bulk.shared::cluster.global.mbarrier::complete_tx::bytes " \
                 "[%0], [%1], %2, [%3];"                                              \
                 :: "r"(dst), "l"(src), "r"(bytes), "r"(bar) : "memory")
#define FENCE_ASYNC_SHARED() asm volatile("fence.proxy.async.shared::cta;" ::: "memory")

__device__ __forceinline__ void ldsm4(uint32_t r[4], uint32_t addr) {
    asm volatile("ldmatrix.sync.aligned.m8n8.x4.shared.b16 {%0,%1,%2,%3}, [%4];"
                 : "=r"(r[0]), "=r"(r[1]), "=r"(r[2]), "=r"(r[3]) : "r"(addr));
}
__device__ __forceinline__ void mma16816(float c[4], const uint32_t a[4], const uint32_t* b) {
    asm volatile(
        "mma.sync.aligned.m16n8k16.row.col.f32.f16.f16.f32 "
        "{%0,%1,%2,%3}, {%4,%5,%6,%7}, {%8,%9}, {%0,%1,%2,%3};"
        : "+f"(c[0]), "+f"(c[1]), "+f"(c[2]), "+f"(c[3])
        : "r"(a[0]), "r"(a[1]), "r"(a[2]), "r"(a[3]), "r"(b[0]), "r"(b[1]));
}

// ---------- activation ----------
__device__ __forceinline__ float act_clip(float h, int f, float mx) {
    float o;
    if (f == 0) {
        o = fmaxf(h, 0.0f);
    } else if (f == 1) {
        o = 1.0f / (1.0f + expf(-h));
    } else if (f == 2) {
        o = tanhf(h);
    } else if (f == 3) {
        o = (h > 0.0f) ? h : 0.1f * h;
    } else {
        const float lam = 1.0507009873554805f;
        const float alp = 1.6732632423543772f;
        o = (h > 0.0f) ? lam * h : lam * alp * expm1f(h);
    }
    return fminf(o, mx);
}

__device__ __forceinline__ uint32_t pack_h2(float x0, float x1) {
    __half2 h = __floats2half2_rn(x0, x1);
    return *(uint32_t*)&h;
}

__device__ __forceinline__ uint32_t blk_off(int r, int q) {
    return (uint32_t)(r * 64 + ((q * 16) ^ ((r & 6) << 3)));
}

// ---------- merged split: fp32 -> blocked hi/lo fp16 ----------
__global__ __launch_bounds__(256)
void split_all_kernel(const float* __restrict__ input,
                      const float* __restrict__ W_in,
                      const float* __restrict__ W_h,
                      const float* __restrict__ W_out,
                      char* __restrict__ ablk, char* __restrict__ wblk)
{
    int idx = blockIdx.x * 256 + threadIdx.x;
    const float* src;
    char* dst;
    int row;
    if (idx < BATCH * 64) {
        src = input; dst = ablk; row = idx >> 6;
    } else if (idx < (BATCH + 512) * 64) {
        idx -= BATCH * 64;
        src = W_in; dst = wblk; row = idx >> 6;
    } else if (idx < (BATCH + 512 + 2048) * 64) {
        idx -= (BATCH + 512) * 64;
        src = W_h; dst = wblk + (size_t)4 * TILE_B; row = idx >> 6;
    } else if (idx < (BATCH + 512 + 2048 + 128) * 64) {
        idx -= (BATCH + 512 + 2048) * 64;
        src = W_out; dst = wblk + (size_t)20 * TILE_B; row = idx >> 6;
    } else {
        return;
    }
    const int h8 = idx & 63;
    const int k0 = h8 * 8;
    const int c  = k0 >> 5;
    const int q  = (k0 >> 3) & 3;
    const int t  = row >> 7;
    const int r  = row & 127;

    float4 a = *(const float4*)(src + (size_t)row * 512 + k0);
    float4 b = *(const float4*)(src + (size_t)row * 512 + k0 + 4);
    float x[8] = {a.x, a.y, a.z, a.w, b.x, b.y, b.z, b.w};
    uint32_t hw[4], lw[4];
#pragma unroll
    for (int i = 0; i < 4; i++) {
        float h0 = __half2float(__float2half_rn(x[2 * i]));
        float h1 = __half2float(__float2half_rn(x[2 * i + 1]));
        hw[i] = pack_h2(x[2 * i], x[2 * i + 1]);
        lw[i] = pack_h2(x[2 * i] - h0, x[2 * i + 1] - h1);
    }
    char* base = dst + (size_t)t * TILE_B + (size_t)c * CHUNK_B;
    const uint32_t off = blk_off(r, q);
    *(uint4*)(base + off)           = make_uint4(hw[0], hw[1], hw[2], hw[3]);
    *(uint4*)(base + PLANE_B + off) = make_uint4(lw[0], lw[1], lw[2], lw[3]);
}

// ============================================================
// C[128,64] tile of act(A @ W^T + b). K = 512 (16 chunks).
// 8 warps 4(M)x2(N); warp tile 32x32. 3-stage cp.async.bulk ring.
// Stage 24 KB: A(hi+lo) 16K | Bh 4K | Bl 4K. 3 CTAs/SM.
// ============================================================
template<bool OUT_FP32>
__global__ __launch_bounds__(256, 3)
void bnn_gemm_kernel(const char* __restrict__ Ablk,
                     const char* __restrict__ Wblk,
                     const float* __restrict__ bias,
                     const int* __restrict__ fid,
                     const float* __restrict__ mcap,
                     float* __restrict__ OutF,
                     char* __restrict__ Oblk)
{
    extern __shared__ char smem[];
    constexpr int NCHUNK = 16;
    constexpr int STAGE  = 24576;
    constexpr int AL_OFF = 8192;
    constexpr int BH_OFF = 16384;
    constexpr int BL_OFF = 20480;

    const int tid  = threadIdx.x;
    const int lane = tid & 31;
    const int wid  = tid >> 5;
    const int mtile = blockIdx.y;
    const int ntile = blockIdx.x;          // 64-col tile
    const uint32_t sb     = smem_u32(smem);
    const uint32_t s_full = sb;            // 3 full barriers  @ 0, 8, 16
    const uint32_t s_empt = sb + 24;       // 3 empty barriers @ 24, 32, 40
    const uint32_t s_stg  = sb + 128;

    const int mw = (wid & 3) * 32;         // warp M offset (4 rows of warps)
    const int nw = (wid >> 2) * 32;        // warp N offset (2 cols of warps)

    const int lA_r = (lane & 7) + ((lane >> 3) & 1) * 8;
    const int lA_c = (lane >> 4) & 1;
    const int lB_r = (lane & 7) + ((lane >> 4) & 1) * 8;
    const int lB_c = (lane >> 3) & 1;

    const uint32_t swzA = (uint32_t)((lA_r & 6) << 3);
    const uint32_t swzB = (uint32_t)((lB_r & 6) << 3);
    uint32_t rowA[2], rowB[2];
#pragma unroll
    for (int mi = 0; mi < 2; mi++) rowA[mi] = (uint32_t)((mw + mi * 16 + lA_r) * 64);
#pragma unroll
    for (int t = 0; t < 2; t++)    rowB[t]  = (uint32_t)((nw + t * 16 + lB_r) * 64);

    float acc[2][4][4];
#pragma unroll
    for (int i = 0; i < 2; i++)
#pragma unroll
        for (int j = 0; j < 4; j++)
#pragma unroll
            for (int v = 0; v < 4; v++) acc[i][j][v] = 0.0f;

    const char* Asrc = Ablk + (size_t)mtile * TILE_B;
    // B source: half (64 rows) of blocked tile (ntile>>1); row offset (ntile&1)*64
    const char* Wsrc = Wblk + (size_t)(ntile >> 1) * TILE_B + (ntile & 1) * 4096;

    // ---- init barriers + prologue bulk loads (chunks 0,1,2) ----
    if (tid == 0) {
#pragma unroll
        for (int s = 0; s < 3; s++) {
            MBARRIER_INIT(s_full + s * 8, 1);
            MBARRIER_INIT(s_empt + s * 8, 8);      // one arrive per warp
        }
    }
    FENCE_ASYNC_SHARED();
    __syncthreads();
    if (tid == 0) {
#pragma unroll
        for (int s = 0; s < 3; s++) {
            const uint32_t bar = s_full + s * 8;
            const uint32_t stg = s_stg + s * STAGE;
            MBARRIER_EXPECT_TX(bar, 24576);
            CP_BULK(stg,          Asrc + (size_t)s * CHUNK_B, 16384, bar);
            CP_BULK(stg + BH_OFF, Wsrc + (size_t)s * CHUNK_B, 4096, bar);
            CP_BULK(stg + BL_OFF, Wsrc + (size_t)s * CHUNK_B + PLANE_B, 4096, bar);
        }
    }

#pragma unroll
    for (int c = 0; c < NCHUNK; c++) {
        const int s   = c % 3;                 // compile-time stage
        const int par = (c / 3) & 1;           // compile-time parity
        MBARRIER_WAIT_PARITY(s_full + s * 8, par);

        const uint32_t stg = s_stg + s * STAGE;

#pragma unroll
        for (int ks = 0; ks < 2; ks++) {
            const uint32_t swA = (uint32_t)((ks * 2 + lA_c) * 16) ^ swzA;
            const uint32_t swB = (uint32_t)((ks * 2 + lB_c) * 16) ^ swzB;

            uint32_t ah[2][4], al[2][4];
#pragma unroll
            for (int mi = 0; mi < 2; mi++) {
                ldsm4(ah[mi], stg + rowA[mi] + swA);
                ldsm4(al[mi], stg + AL_OFF + rowA[mi] + swA);
            }
            uint32_t bh0[4], bh1[4], bl0[4], bl1[4];
            ldsm4(bh0, stg + BH_OFF + rowB[0] + swB);
            ldsm4(bh1, stg + BH_OFF + rowB[1] + swB);
            ldsm4(bl0, stg + BL_OFF + rowB[0] + swB);
            ldsm4(bl1, stg + BL_OFF + rowB[1] + swB);

            // last smem read of this stage happens at ks==1: release early
            if (ks == 1 && lane == 0) MBARRIER_ARRIVE(s_empt + s * 8);

            const uint32_t* bhp[4] = {bh0, bh0 + 2, bh1, bh1 + 2};
            const uint32_t* blp[4] = {bl0, bl0 + 2, bl1, bl1 + 2};

            // hh, hl, lh — mi-inner for accumulator reuse distance
#pragma unroll
            for (int ni = 0; ni < 4; ni++)
#pragma unroll
                for (int mi = 0; mi < 2; mi++) mma16816(acc[mi][ni], ah[mi], bhp[ni]);
#pragma unroll
            for (int ni = 0; ni < 4; ni++)
#pragma unroll
                for (int mi = 0; mi < 2; mi++) mma16816(acc[mi][ni], ah[mi], blp[ni]);
#pragma unroll
            for (int ni = 0; ni < 4; ni++)
#pragma unroll
                for (int mi = 0; mi < 2; mi++) mma16816(acc[mi][ni], al[mi], bhp[ni]);
        }

        // producer: refill stage s with chunk c+3 once all 8 warps released it
        if (c + 3 < NCHUNK) {
            if (tid == 0) {
                MBARRIER_WAIT_PARITY(s_empt + s * 8, par);
                const uint32_t bar = s_full + s * 8;
                MBARRIER_EXPECT_TX(bar, 24576);
                CP_BULK(stg,          Asrc + (size_t)(c + 3) * CHUNK_B, 16384, bar);
                CP_BULK(stg + BH_OFF, Wsrc + (size_t)(c + 3) * CHUNK_B, 4096, bar);
                CP_BULK(stg + BL_OFF, Wsrc + (size_t)(c + 3) * CHUNK_B + PLANE_B, 4096, bar);
            }
        }
    }

    // ---------- epilogue ----------
    const int colq = (lane & 3) * 2;
#pragma unroll
    for (int ni = 0; ni < 4; ni++) {
        const int col = ntile * 64 + nw + ni * 8 + colq;
        const float2 b2 = *(const float2*)(bias + col);
        const int2   f2 = *(const int2*)(fid + col);
        const float2 m2 = *(const float2*)(mcap + col);
        const int oc = col >> 5;
        const int oq = (col >> 3) & 3;
        const int ob = (col & 7) * 2;
#pragma unroll
        for (int mi = 0; mi < 2; mi++) {
#pragma unroll
            for (int h = 0; h < 2; h++) {
                const int row = mtile * 128 + mw + mi * 16 + (lane >> 2) + h * 8;
                const float r0 = act_clip(acc[mi][ni][h * 2 + 0] + b2.x, f2.x, m2.x);
                const float r1 = act_clip(acc[mi][ni][h * 2 + 1] + b2.y, f2.y, m2.y);
                if (OUT_FP32) {
                    *(float2*)(OutF + (size_t)row * 128 + col) = make_float2(r0, r1);
                } else {
                    const int rr = row & 127;
                    char* base = Oblk + (size_t)(row >> 7) * TILE_B + (size_t)oc * CHUNK_B;
                    const uint32_t off = blk_off(rr, oq) + ob;
                    const float h0 = __half2float(__float2half_rn(r0));
                    const float h1 = __half2float(__float2half_rn(r1));
                    *(uint32_t*)(base + off)           = pack_h2(r0, r1);
                    *(uint32_t*)(base + PLANE_B + off) = pack_h2(r0 - h0, r1 - h1);
                }
            }
        }
    }
}

// ============================================================
extern "C" void kernel_launch(void* const* d_in, const int* in_sizes, int n_in,
                              void* d_out, int out_size)
{
    const float* input  = (const float*)d_in[0];
    const float* W_in   = (const float*)d_in[1];
    const float* b_in   = (const float*)d_in[2];
    const float* W_h    = (const float*)d_in[3];
    const float* b_h    = (const float*)d_in[4];
    const float* W_out  = (const float*)d_in[5];
    const float* b_out  = (const float*)d_in[6];
    const float* m_in   = (const float*)d_in[7];
    const float* m_h    = (const float*)d_in[8];
    const float* m_out  = (const float*)d_in[9];
    const int*   fid_in  = (const int*)d_in[10];
    const int*   fid_h   = (const int*)d_in[11];
    const int*   fid_out = (const int*)d_in[12];
    float* out = (float*)d_out;

    char *ablk0, *ablk1, *wblk;
    cudaGetSymbolAddress((void**)&ablk0, g_ablk0);
    cudaGetSymbolAddress((void**)&ablk1, g_ablk1);
    cudaGetSymbolAddress((void**)&wblk, g_wblk);

    constexpr int SMEM = 128 + 3 * 24576;   // 73856 -> 3 CTAs/SM
    cudaFuncSetAttribute(bnn_gemm_kernel<false>,
                         cudaFuncAttributeMaxDynamicSharedMemorySize, SMEM);
    cudaFuncSetAttribute(bnn_gemm_kernel<true>,
                         cudaFuncAttributeMaxDynamicSharedMemorySize, SMEM);

    const int B = BATCH, X = XDIM;
    char* w_in_blk  = wblk;
    char* w_h_blk   = wblk + (size_t)4 * TILE_B;
    char* w_out_blk = wblk + (size_t)20 * TILE_B;

    const int total_slots = (B + 512 + 2048 + 128) * 64;
    split_all_kernel<<<(total_slots + 255) / 256, 256>>>(
        input, W_in, W_h, W_out, ablk0, wblk);

    dim3 blk(256);
    dim3 grid512(8, B / 128);          // 8 x 64-col tiles
    dim3 grid128(2, B / 128);          // 2 x 64-col tiles

    bnn_gemm_kernel<false><<<grid512, blk, SMEM>>>(
        ablk0, w_in_blk, b_in, fid_in, m_in, nullptr, ablk1);

    char *cur = ablk1, *nxt = ablk0;
    for (int i = 0; i < 4; i++) {
        bnn_gemm_kernel<false><<<grid512, blk, SMEM>>>(
            cur, w_h_blk + (size_t)i * 4 * TILE_B,
            b_h + i * X, fid_h + i * X, m_h + i * X, nullptr, nxt);
        char* t = cur; cur = nxt; nxt = t;
    }

    bnn_gemm_kernel<true><<<grid128, blk, SMEM>>>(
        cur, w_out_blk, b_out, fid_out, m_out, out, nullptr);
}

// round 12
// speedup vs baseline: 1.2524x; 1.0010x over previous
#include <cuda_runtime.h>
#include <cuda_fp16.h>
#include <math.h>
#include <stdint.h>

// ============================================================
// mma.sync (HMMA) fp16-split GEMM chain for the 6-layer MLP.
// fp32 x fp32 emulated as (hi+lo fp16): hh + hl + lh, fp32 accum.
// R11: register-lean 128x64 CTA tile, warp tile 32x32, 3 CTAs/SM
//      (24 warps/SM) — warp-count latency hiding.
// ============================================================

#define BATCH 65536
#define XDIM 512

// Blocked tile: [tile][chunk 0..15][plane hi/lo][128 rows x 64 B], pre-swizzled.
#define PLANE_B   8192
#define CHUNK_B   16384
#define TILE_B    262144

// ---------- scratch (no cudaMalloc allowed) ----------
__device__ __align__(256) char g_ablk0[(size_t)512 * TILE_B];
__device__ __align__(256) char g_ablk1[(size_t)512 * TILE_B];
__device__ __align__(256) char g_wblk[(size_t)21 * TILE_B];

// ---------- PTX helpers ----------
__device__ __forceinline__ uint32_t smem_u32(const void* p) {
    uint32_t a;
    asm("{ .reg .u64 t; cvta.to.shared.u64 t, %1; cvt.u32.u64 %0, t; }" : "=r"(a) : "l"(p));
    return a;
}
#define MBARRIER_INIT(addr, cnt) \
    asm volatile("mbarrier.init.shared.b64 [%0], %1;" :: "r"(addr), "r"(cnt) : "memory")
#define MBARRIER_EXPECT_TX(addr, bytes) \
    asm volatile("mbarrier.arrive.expect_tx.shared.b64 _, [%0], %1;" :: "r"(addr), "r"(bytes) : "memory")
#define MBARRIER_ARRIVE(addr) \
    asm volatile("mbarrier.arrive.release.cta.shared.b64 _, [%0];" :: "r"(addr) : "memory")
#define MBARRIER_WAIT_PARITY(addr, parity) do {                                      \
    uint32_t _m = (addr); uint32_t _p = (parity); uint32_t _d;                        \
    asm volatile("{\n\t.reg .pred p;\n\t"                                             \
        "mbarrier.try_wait.parity.acquire.cta.shared::cta.b64 p, [%1], %2;\n\t"       \
        "selp.b32 %0, 1, 0, p;\n\t}" : "=r"(_d) : "r"(_m), "r"(_p) : "memory");       \
    if (!_d) {                                                                        \
        asm volatile("{\n\t.reg .pred P1;\n\t"                                        \
            "W_%=:\n\t"                                                               \
            "mbarrier.try_wait.parity.acquire.cta.shared::cta.b64 P1, [%0], %1, 0x989680;\n\t" \
            "@P1 bra.uni D_%=;\n\t"                                                   \
            "bra.uni W_%=;\n\t"                                                       \
            "D_%=:\n\t}" :: "r"(_m), "r"(_p) : "memory");                             \
    }                                                                                 \
} while (0)
#define CP_BULK(dst, src, bytes, bar)                                                 \
    asm volatile("cp.async.bulk.shared::cluster.global.mbarrier::complete_tx::bytes " \
                 "[%0], [%1], %2, [%3];"                                              \
                 :: "r"(dst), "l"(src), "r"(bytes), "r"(bar) : "memory")
#define FENCE_ASYNC_SHARED() asm volatile("fence.proxy.async.shared::cta;" ::: "memory")

__device__ __forceinline__ void ldsm4(uint32_t r[4], uint32_t addr) {
    asm volatile("ldmatrix.sync.aligned.m8n8.x4.shared.b16 {%0,%1,%2,%3}, [%4];"
                 : "=r"(r[0]), "=r"(r[1]), "=r"(r[2]), "=r"(r[3]) : "r"(addr));
}
__device__ __forceinline__ void mma16816(float c[4], const uint32_t a[4], const uint32_t* b) {
    asm volatile(
        "mma.sync.aligned.m16n8k16.row.col.f32.f16.f16.f32 "
        "{%0,%1,%2,%3}, {%4,%5,%6,%7}, {%8,%9}, {%0,%1,%2,%3};"
        : "+f"(c[0]), "+f"(c[1]), "+f"(c[2]), "+f"(c[3])
        : "r"(a[0]), "r"(a[1]), "r"(a[2]), "r"(a[3]), "r"(b[0]), "r"(b[1]));
}

// ---------- activation ----------
__device__ __forceinline__ float act_clip(float h, int f, float mx) {
    float o;
    if (f == 0) {
        o = fmaxf(h, 0.0f);
    } else if (f == 1) {
        o = 1.0f / (1.0f + expf(-h));
    } else if (f == 2) {
        o = tanhf(h);
    } else if (f == 3) {
        o = (h > 0.0f) ? h : 0.1f * h;
    } else {
        const float lam = 1.0507009873554805f;
        const float alp = 1.6732632423543772f;
        o = (h > 0.0f) ? lam * h : lam * alp * expm1f(h);
    }
    return fminf(o, mx);
}

__device__ __forceinline__ uint32_t pack_h2(float x0, float x1) {
    __half2 h = __floats2half2_rn(x0, x1);
    return *(uint32_t*)&h;
}

__device__ __forceinline__ uint32_t blk_off(int r, int q) {
    return (uint32_t)(r * 64 + ((q * 16) ^ ((r & 6) << 3)));
}

// ---------- merged split: fp32 -> blocked hi/lo fp16 ----------
__global__ __launch_bounds__(256)
void split_all_kernel(const float* __restrict__ input,
                      const float* __restrict__ W_in,
                      const float* __restrict__ W_h,
                      const float* __restrict__ W_out,
                      char* __restrict__ ablk, char* __restrict__ wblk)
{
    int idx = blockIdx.x * 256 + threadIdx.x;
    const float* src;
    char* dst;
    int row;
    if (idx < BATCH * 64) {
        src = input; dst = ablk; row = idx >> 6;
    } else if (idx < (BATCH + 512) * 64) {
        idx -= BATCH * 64;
        src = W_in; dst = wblk; row = idx >> 6;
    } else if (idx < (BATCH + 512 + 2048) * 64) {
        idx -= (BATCH + 512) * 64;
        src = W_h; dst = wblk + (size_t)4 * TILE_B; row = idx >> 6;
    } else if (idx < (BATCH + 512 + 2048 + 128) * 64) {
        idx -= (BATCH + 512 + 2048) * 64;
        src = W_out; dst = wblk + (size_t)20 * TILE_B; row = idx >> 6;
    } else {
        return;
    }
    const int h8 = idx & 63;
    const int k0 = h8 * 8;
    const int c  = k0 >> 5;
    const int q  = (k0 >> 3) & 3;
    const int t  = row >> 7;
    const int r  = row & 127;

    float4 a = *(const float4*)(src + (size_t)row * 512 + k0);
    float4 b = *(const float4*)(src + (size_t)row * 512 + k0 + 4);
    float x[8] = {a.x, a.y, a.z, a.w, b.x, b.y, b.z, b.w};
    uint32_t hw[4], lw[4];
#pragma unroll
    for (int i = 0; i < 4; i++) {
        float h0 = __half2float(__float2half_rn(x[2 * i]));
        float h1 = __half2float(__float2half_rn(x[2 * i + 1]));
        hw[i] = pack_h2(x[2 * i], x[2 * i + 1]);
        lw[i] = pack_h2(x[2 * i] - h0, x[2 * i + 1] - h1);
    }
    char* base = dst + (size_t)t * TILE_B + (size_t)c * CHUNK_B;
    const uint32_t off = blk_off(r, q);
    *(uint4*)(base + off)           = make_uint4(hw[0], hw[1], hw[2], hw[3]);
    *(uint4*)(base + PLANE_B + off) = make_uint4(lw[0], lw[1], lw[2], lw[3]);
}

// ============================================================
// C[128,64] tile of act(A @ W^T + b). K = 512 (16 chunks).
// 8 warps 4(M)x2(N); warp tile 32x32. 3-stage cp.async.bulk ring.
// Stage 24 KB: A(hi+lo) 16K | Bh 4K | Bl 4K. 3 CTAs/SM.
// ============================================================
template<bool OUT_FP32>
__global__ __launch_bounds__(256, 3)
void bnn_gemm_kernel(const char* __restrict__ Ablk,
                     const char* __restrict__ Wblk,
                     const float* __restrict__ bias,
                     const int* __restrict__ fid,
                     const float* __restrict__ mcap,
                     float* __restrict__ OutF,
                     char* __restrict__ Oblk)
{
    extern __shared__ char smem[];
    constexpr int NCHUNK = 16;
    constexpr int STAGE  = 24576;
    constexpr int AL_OFF = 8192;
    constexpr int BH_OFF = 16384;
    constexpr int BL_OFF = 20480;

    const int tid  = threadIdx.x;
    const int lane = tid & 31;
    const int wid  = tid >> 5;
    const int mtile = blockIdx.y;
    const int ntile = blockIdx.x;          // 64-col tile
    const uint32_t sb     = smem_u32(smem);
    const uint32_t s_full = sb;            // 3 full barriers  @ 0, 8, 16
    const uint32_t s_empt = sb + 24;       // 3 empty barriers @ 24, 32, 40
    const uint32_t s_stg  = sb + 128;

    const int mw = (wid & 3) * 32;         // warp M offset (4 rows of warps)
    const int nw = (wid >> 2) * 32;        // warp N offset (2 cols of warps)

    const int lA_r = (lane & 7) + ((lane >> 3) & 1) * 8;
    const int lA_c = (lane >> 4) & 1;
    const int lB_r = (lane & 7) + ((lane >> 4) & 1) * 8;
    const int lB_c = (lane >> 3) & 1;

    const uint32_t swzA = (uint32_t)((lA_r & 6) << 3);
    const uint32_t swzB = (uint32_t)((lB_r & 6) << 3);
    uint32_t rowA[2], rowB[2];
#pragma unroll
    for (int mi = 0; mi < 2; mi++) rowA[mi] = (uint32_t)((mw + mi * 16 + lA_r) * 64);
#pragma unroll
    for (int t = 0; t < 2; t++)    rowB[t]  = (uint32_t)((nw + t * 16 + lB_r) * 64);

    float acc[2][4][4];
#pragma unroll
    for (int i = 0; i < 2; i++)
#pragma unroll
        for (int j = 0; j < 4; j++)
#pragma unroll
            for (int v = 0; v < 4; v++) acc[i][j][v] = 0.0f;

    const char* Asrc = Ablk + (size_t)mtile * TILE_B;
    // B source: half (64 rows) of blocked tile (ntile>>1); row offset (ntile&1)*64
    const char* Wsrc = Wblk + (size_t)(ntile >> 1) * TILE_B + (ntile & 1) * 4096;

    // ---- init barriers + prologue bulk loads (chunks 0,1,2) ----
    if (tid == 0) {
#pragma unroll
        for (int s = 0; s < 3; s++) {
            MBARRIER_INIT(s_full + s * 8, 1);
            MBARRIER_INIT(s_empt + s * 8, 8);      // one arrive per warp
        }
    }
    FENCE_ASYNC_SHARED();
    __syncthreads();
    if (tid == 0) {
#pragma unroll
        for (int s = 0; s < 3; s++) {
            const uint32_t bar = s_full + s * 8;
            const uint32_t stg = s_stg + s * STAGE;
            MBARRIER_EXPECT_TX(bar, 24576);
            CP_BULK(stg,          Asrc + (size_t)s * CHUNK_B, 16384, bar);
            CP_BULK(stg + BH_OFF, Wsrc + (size_t)s * CHUNK_B, 4096, bar);
            CP_BULK(stg + BL_OFF, Wsrc + (size_t)s * CHUNK_B + PLANE_B, 4096, bar);
        }
    }

#pragma unroll
    for (int c = 0; c < NCHUNK; c++) {
        const int s   = c % 3;                 // compile-time stage
        const int par = (c / 3) & 1;           // compile-time parity
        MBARRIER_WAIT_PARITY(s_full + s * 8, par);

        const uint32_t stg = s_stg + s * STAGE;

#pragma unroll
        for (int ks = 0; ks < 2; ks++) {
            const uint32_t swA = (uint32_t)((ks * 2 + lA_c) * 16) ^ swzA;
            const uint32_t swB = (uint32_t)((ks * 2 + lB_c) * 16) ^ swzB;

            uint32_t ah[2][4], al[2][4];
#pragma unroll
            for (int mi = 0; mi < 2; mi++) {
                ldsm4(ah[mi], stg + rowA[mi] + swA);
                ldsm4(al[mi], stg + AL_OFF + rowA[mi] + swA);
            }
            uint32_t bh0[4], bh1[4], bl0[4], bl1[4];
            ldsm4(bh0, stg + BH_OFF + rowB[0] + swB);
            ldsm4(bh1, stg + BH_OFF + rowB[1] + swB);
            ldsm4(bl0, stg + BL_OFF + rowB[0] + swB);
            ldsm4(bl1, stg + BL_OFF + rowB[1] + swB);

            // last smem read of this stage happens at ks==1: release early
            if (ks == 1 && lane == 0) MBARRIER_ARRIVE(s_empt + s * 8);

            const uint32_t* bhp[4] = {bh0, bh0 + 2, bh1, bh1 + 2};
            const uint32_t* blp[4] = {bl0, bl0 + 2, bl1, bl1 + 2};

            // hh, hl, lh — mi-inner for accumulator reuse distance
#pragma unroll
            for (int ni = 0; ni < 4; ni++)
#pragma unroll
                for (int mi = 0; mi < 2; mi++) mma16816(acc[mi][ni], ah[mi], bhp[ni]);
#pragma unroll
            for (int ni = 0; ni < 4; ni++)
#pragma unroll
                for (int mi = 0; mi < 2; mi++) mma16816(acc[mi][ni], ah[mi], blp[ni]);
#pragma unroll
            for (int ni = 0; ni < 4; ni++)
#pragma unroll
                for (int mi = 0; mi < 2; mi++) mma16816(acc[mi][ni], al[mi], bhp[ni]);
        }

        // producer: refill stage s with chunk c+3 once all 8 warps released it
        if (c + 3 < NCHUNK) {
            if (tid == 0) {
                MBARRIER_WAIT_PARITY(s_empt + s * 8, par);
                const uint32_t bar = s_full + s * 8;
                MBARRIER_EXPECT_TX(bar, 24576);
                CP_BULK(stg,          Asrc + (size_t)(c + 3) * CHUNK_B, 16384, bar);
                CP_BULK(stg + BH_OFF, Wsrc + (size_t)(c + 3) * CHUNK_B, 4096, bar);
                CP_BULK(stg + BL_OFF, Wsrc + (size_t)(c + 3) * CHUNK_B + PLANE_B, 4096, bar);
            }
        }
    }

    // ---------- epilogue ----------
    const int colq = (lane & 3) * 2;
#pragma unroll
    for (int ni = 0; ni < 4; ni++) {
        const int col = ntile * 64 + nw + ni * 8 + colq;
        const float2 b2 = *(const float2*)(bias + col);
        const int2   f2 = *(const int2*)(fid + col);
        const float2 m2 = *(const float2*)(mcap + col);
        const int oc = col >> 5;
        const int oq = (col >> 3) & 3;
        const int ob = (col & 7) * 2;
#pragma unroll
        for (int mi = 0; mi < 2; mi++) {
#pragma unroll
            for (int h = 0; h < 2; h++) {
                const int row = mtile * 128 + mw + mi * 16 + (lane >> 2) + h * 8;
                const float r0 = act_clip(acc[mi][ni][h * 2 + 0] + b2.x, f2.x, m2.x);
                const float r1 = act_clip(acc[mi][ni][h * 2 + 1] + b2.y, f2.y, m2.y);
                if (OUT_FP32) {
                    *(float2*)(OutF + (size_t)row * 128 + col) = make_float2(r0, r1);
                } else {
                    const int rr = row & 127;
                    char* base = Oblk + (size_t)(row >> 7) * TILE_B + (size_t)oc * CHUNK_B;
                    const uint32_t off = blk_off(rr, oq) + ob;
                    const float h0 = __half2float(__float2half_rn(r0));
                    const float h1 = __half2float(__float2half_rn(r1));
                    *(uint32_t*)(base + off)           = pack_h2(r0, r1);
                    *(uint32_t*)(base + PLANE_B + off) = pack_h2(r0 - h0, r1 - h1);
                }
            }
        }
    }
}

// ============================================================
extern "C" void kernel_launch(void* const* d_in, const int* in_sizes, int n_in,
                              void* d_out, int out_size)
{
    const float* input  = (const float*)d_in[0];
    const float* W_in   = (const float*)d_in[1];
    const float* b_in   = (const float*)d_in[2];
    const float* W_h    = (const float*)d_in[3];
    const float* b_h    = (const float*)d_in[4];
    const float* W_out  = (const float*)d_in[5];
    const float* b_out  = (const float*)d_in[6];
    const float* m_in   = (const float*)d_in[7];
    const float* m_h    = (const float*)d_in[8];
    const float* m_out  = (const float*)d_in[9];
    const int*   fid_in  = (const int*)d_in[10];
    const int*   fid_h   = (const int*)d_in[11];
    const int*   fid_out = (const int*)d_in[12];
    float* out = (float*)d_out;

    char *ablk0, *ablk1, *wblk;
    cudaGetSymbolAddress((void**)&ablk0, g_ablk0);
    cudaGetSymbolAddress((void**)&ablk1, g_ablk1);
    cudaGetSymbolAddress((void**)&wblk, g_wblk);

    constexpr int SMEM = 128 + 3 * 24576;   // 73856 -> 3 CTAs/SM
    cudaFuncSetAttribute(bnn_gemm_kernel<false>,
                         cudaFuncAttributeMaxDynamicSharedMemorySize, SMEM);
    cudaFuncSetAttribute(bnn_gemm_kernel<true>,
                         cudaFuncAttributeMaxDynamicSharedMemorySize, SMEM);

    const int B = BATCH, X = XDIM;
    char* w_in_blk  = wblk;
    char* w_h_blk   = wblk + (size_t)4 * TILE_B;
    char* w_out_blk = wblk + (size_t)20 * TILE_B;

    const int total_slots = (B + 512 + 2048 + 128) * 64;
    split_all_kernel<<<(total_slots + 255) / 256, 256>>>(
        input, W_in, W_h, W_out, ablk0, wblk);

    dim3 blk(256);
    dim3 grid512(8, B / 128);          // 8 x 64-col tiles
    dim3 grid128(2, B / 128);          // 2 x 64-col tiles

    bnn_gemm_kernel<false><<<grid512, blk, SMEM>>>(
        ablk0, w_in_blk, b_in, fid_in, m_in, nullptr, ablk1);

    char *cur = ablk1, *nxt = ablk0;
    for (int i = 0; i < 4; i++) {
        bnn_gemm_kernel<false><<<grid512, blk, SMEM>>>(
            cur, w_h_blk + (size_t)i * 4 * TILE_B,
            b_h + i * X, fid_h + i * X, m_h + i * X, nullptr, nxt);
        char* t = cur; cur = nxt; nxt = t;
    }

    bnn_gemm_kernel<true><<<grid128, blk, SMEM>>>(
        cur, w_out_blk, b_out, fid_out, m_out, out, nullptr);
}

// round 14
// speedup vs baseline: 1.2527x; 1.0003x over previous
#include <cuda_runtime.h>
#include <cuda_fp16.h>
#include <math.h>
#include <stdint.h>

// ============================================================
// mma.sync (HMMA) fp16-split GEMM chain for the 6-layer MLP.
// fp32 x fp32 emulated as (hi+lo fp16): hh + hl + lh, fp32 accum.
// R11: register-lean 128x64 CTA tile, warp tile 32x32, 3 CTAs/SM
//      (24 warps/SM) — warp-count latency hiding.
// ============================================================

#define BATCH 65536
#define XDIM 512

// Blocked tile: [tile][chunk 0..15][plane hi/lo][128 rows x 64 B], pre-swizzled.
#define PLANE_B   8192
#define CHUNK_B   16384
#define TILE_B    262144

// ---------- scratch (no cudaMalloc allowed) ----------
__device__ __align__(256) char g_ablk0[(size_t)512 * TILE_B];
__device__ __align__(256) char g_ablk1[(size_t)512 * TILE_B];
__device__ __align__(256) char g_wblk[(size_t)21 * TILE_B];

// ---------- PTX helpers ----------
__device__ __forceinline__ uint32_t smem_u32(const void* p) {
    uint32_t a;
    asm("{ .reg .u64 t; cvta.to.shared.u64 t, %1; cvt.u32.u64 %0, t; }" : "=r"(a) : "l"(p));
    return a;
}
#define MBARRIER_INIT(addr, cnt) \
    asm volatile("mbarrier.init.shared.b64 [%0], %1;" :: "r"(addr), "r"(cnt) : "memory")
#define MBARRIER_EXPECT_TX(addr, bytes) \
    asm volatile("mbarrier.arrive.expect_tx.shared.b64 _, [%0], %1;" :: "r"(addr), "r"(bytes) : "memory")
#define MBARRIER_ARRIVE(addr) \
    asm volatile("mbarrier.arrive.release.cta.shared.b64 _, [%0];" :: "r"(addr) : "memory")
#define MBARRIER_WAIT_PARITY(addr, parity) do {                                      \
    uint32_t _m = (addr); uint32_t _p = (parity); uint32_t _d;                        \
    asm volatile("{\n\t.reg .pred p;\n\t"                                             \
        "mbarrier.try_wait.parity.acquire.cta.shared::cta.b64 p, [%1], %2;\n\t"       \
        "selp.b32 %0, 1, 0, p;\n\t}" : "=r"(_d) : "r"(_m), "r"(_p) : "memory");       \
    if (!_d) {                                                                        \
        asm volatile("{\n\t.reg .pred P1;\n\t"                                        \
            "W_%=:\n\t"                                                               \
            "mbarrier.try_wait.parity.acquire.cta.shared::cta.b64 P1, [%0], %1, 0x989680;\n\t" \
            "@P1 bra.uni D_%=;\n\t"                                                   \
            "bra.uni W_%=;\n\t"                                                       \
            "D_%=:\n\t}" :: "r"(_m), "r"(_p) : "memory");                             \
    }                                                                                 \
} while (0)
#define CP_BULK(dst, src, bytes, bar)                                                 \
    asm volatile("cp.async.bulk.shared::cluster.global.mbarrier::complete_tx::bytes " \
                 "[%0], [%1], %2, [%3];"                                              \
                 :: "r"(dst), "l"(src), "r"(bytes), "r"(bar) : "memory")
#define FENCE_ASYNC_SHARED() asm volatile("fence.proxy.async.shared::cta;" ::: "memory")

__device__ __forceinline__ void ldsm4(uint32_t r[4], uint32_t addr) {
    asm volatile("ldmatrix.sync.aligned.m8n8.x4.shared.b16 {%0,%1,%2,%3}, [%4];"
                 : "=r"(r[0]), "=r"(r[1]), "=r"(r[2]), "=r"(r[3]) : "r"(addr));
}
__device__ __forceinline__ void mma16816(float c[4], const uint32_t a[4], const uint32_t* b) {
    asm volatile(
        "mma.sync.aligned.m16n8k16.row.col.f32.f16.f16.f32 "
        "{%0,%1,%2,%3}, {%4,%5,%6,%7}, {%8,%9}, {%0,%1,%2,%3};"
        : "+f"(c[0]), "+f"(c[1]), "+f"(c[2]), "+f"(c[3])
        : "r"(a[0]), "r"(a[1]), "r"(a[2]), "r"(a[3]), "r"(b[0]), "r"(b[1]));
}

// ---------- activation ----------
__device__ __forceinline__ float act_clip(float h, int f, float mx) {
    float o;
    if (f == 0) {
        o = fmaxf(h, 0.0f);
    } else if (f == 1) {
        o = 1.0f / (1.0f + expf(-h));
    } else if (f == 2) {
        o = tanhf(h);
    } else if (f == 3) {
        o = (h > 0.0f) ? h : 0.1f * h;
    } else {
        const float lam = 1.0507009873554805f;
        const float alp = 1.6732632423543772f;
        o = (h > 0.0f) ? lam * h : lam * alp * expm1f(h);
    }
    return fminf(o, mx);
}

__device__ __forceinline__ uint32_t pack_h2(float x0, float x1) {
    __half2 h = __floats2half2_rn(x0, x1);
    return *(uint32_t*)&h;
}

__device__ __forceinline__ uint32_t blk_off(int r, int q) {
    return (uint32_t)(r * 64 + ((q * 16) ^ ((r & 6) << 3)));
}

// ---------- merged split: fp32 -> blocked hi/lo fp16 ----------
__global__ __launch_bounds__(256)
void split_all_kernel(const float* __restrict__ input,
                      const float* __restrict__ W_in,
                      const float* __restrict__ W_h,
                      const float* __restrict__ W_out,
                      char* __restrict__ ablk, char* __restrict__ wblk)
{
    int idx = blockIdx.x * 256 + threadIdx.x;
    const float* src;
    char* dst;
    int row;
    if (idx < BATCH * 64) {
        src = input; dst = ablk; row = idx >> 6;
    } else if (idx < (BATCH + 512) * 64) {
        idx -= BATCH * 64;
        src = W_in; dst = wblk; row = idx >> 6;
    } else if (idx < (BATCH + 512 + 2048) * 64) {
        idx -= (BATCH + 512) * 64;
        src = W_h; dst = wblk + (size_t)4 * TILE_B; row = idx >> 6;
    } else if (idx < (BATCH + 512 + 2048 + 128) * 64) {
        idx -= (BATCH + 512 + 2048) * 64;
        src = W_out; dst = wblk + (size_t)20 * TILE_B; row = idx >> 6;
    } else {
        return;
    }
    const int h8 = idx & 63;
    const int k0 = h8 * 8;
    const int c  = k0 >> 5;
    const int q  = (k0 >> 3) & 3;
    const int t  = row >> 7;
    const int r  = row & 127;

    float4 a = *(const float4*)(src + (size_t)row * 512 + k0);
    float4 b = *(const float4*)(src + (size_t)row * 512 + k0 + 4);
    float x[8] = {a.x, a.y, a.z, a.w, b.x, b.y, b.z, b.w};
    uint32_t hw[4], lw[4];
#pragma unroll
    for (int i = 0; i < 4; i++) {
        float h0 = __half2float(__float2half_rn(x[2 * i]));
        float h1 = __half2float(__float2half_rn(x[2 * i + 1]));
        hw[i] = pack_h2(x[2 * i], x[2 * i + 1]);
        lw[i] = pack_h2(x[2 * i] - h0, x[2 * i + 1] - h1);
    }
    char* base = dst + (size_t)t * TILE_B + (size_t)c * CHUNK_B;
    const uint32_t off = blk_off(r, q);
    *(uint4*)(base + off)           = make_uint4(hw[0], hw[1], hw[2], hw[3]);
    *(uint4*)(base + PLANE_B + off) = make_uint4(lw[0], lw[1], lw[2], lw[3]);
}

// ============================================================
// C[128,64] tile of act(A @ W^T + b). K = 512 (16 chunks).
// 8 warps 4(M)x2(N); warp tile 32x32. 3-stage cp.async.bulk ring.
// Stage 24 KB: A(hi+lo) 16K | Bh 4K | Bl 4K. 3 CTAs/SM.
// ============================================================
template<bool OUT_FP32>
__global__ __launch_bounds__(256, 3)
void bnn_gemm_kernel(const char* __restrict__ Ablk,
                     const char* __restrict__ Wblk,
                     const float* __restrict__ bias,
                     const int* __restrict__ fid,
                     const float* __restrict__ mcap,
                     float* __restrict__ OutF,
                     char* __restrict__ Oblk)
{
    extern __shared__ char smem[];
    constexpr int NCHUNK = 16;
    constexpr int STAGE  = 24576;
    constexpr int AL_OFF = 8192;
    constexpr int BH_OFF = 16384;
    constexpr int BL_OFF = 20480;

    const int tid  = threadIdx.x;
    const int lane = tid & 31;
    const int wid  = tid >> 5;
    const int mtile = blockIdx.y;
    const int ntile = blockIdx.x;          // 64-col tile
    const uint32_t sb     = smem_u32(smem);
    const uint32_t s_full = sb;            // 3 full barriers  @ 0, 8, 16
    const uint32_t s_empt = sb + 24;       // 3 empty barriers @ 24, 32, 40
    const uint32_t s_stg  = sb + 128;

    const int mw = (wid & 3) * 32;         // warp M offset (4 rows of warps)
    const int nw = (wid >> 2) * 32;        // warp N offset (2 cols of warps)

    const int lA_r = (lane & 7) + ((lane >> 3) & 1) * 8;
    const int lA_c = (lane >> 4) & 1;
    const int lB_r = (lane & 7) + ((lane >> 4) & 1) * 8;
    const int lB_c = (lane >> 3) & 1;

    const uint32_t swzA = (uint32_t)((lA_r & 6) << 3);
    const uint32_t swzB = (uint32_t)((lB_r & 6) << 3);
    uint32_t rowA[2], rowB[2];
#pragma unroll
    for (int mi = 0; mi < 2; mi++) rowA[mi] = (uint32_t)((mw + mi * 16 + lA_r) * 64);
#pragma unroll
    for (int t = 0; t < 2; t++)    rowB[t]  = (uint32_t)((nw + t * 16 + lB_r) * 64);

    float acc[2][4][4];
#pragma unroll
    for (int i = 0; i < 2; i++)
#pragma unroll
        for (int j = 0; j < 4; j++)
#pragma unroll
            for (int v = 0; v < 4; v++) acc[i][j][v] = 0.0f;

    const char* Asrc = Ablk + (size_t)mtile * TILE_B;
    // B source: half (64 rows) of blocked tile (ntile>>1); row offset (ntile&1)*64
    const char* Wsrc = Wblk + (size_t)(ntile >> 1) * TILE_B + (ntile & 1) * 4096;

    // ---- init barriers + prologue bulk loads (chunks 0,1,2) ----
    if (tid == 0) {
#pragma unroll
        for (int s = 0; s < 3; s++) {
            MBARRIER_INIT(s_full + s * 8, 1);
            MBARRIER_INIT(s_empt + s * 8, 8);      // one arrive per warp
        }
    }
    FENCE_ASYNC_SHARED();
    __syncthreads();
    if (tid == 0) {
#pragma unroll
        for (int s = 0; s < 3; s++) {
            const uint32_t bar = s_full + s * 8;
            const uint32_t stg = s_stg + s * STAGE;
            MBARRIER_EXPECT_TX(bar, 24576);
            CP_BULK(stg,          Asrc + (size_t)s * CHUNK_B, 16384, bar);
            CP_BULK(stg + BH_OFF, Wsrc + (size_t)s * CHUNK_B, 4096, bar);
            CP_BULK(stg + BL_OFF, Wsrc + (size_t)s * CHUNK_B + PLANE_B, 4096, bar);
        }
    }

#pragma unroll
    for (int c = 0; c < NCHUNK; c++) {
        const int s   = c % 3;                 // compile-time stage
        const int par = (c / 3) & 1;           // compile-time parity
        MBARRIER_WAIT_PARITY(s_full + s * 8, par);

        const uint32_t stg = s_stg + s * STAGE;

#pragma unroll
        for (int ks = 0; ks < 2; ks++) {
            const uint32_t swA = (uint32_t)((ks * 2 + lA_c) * 16) ^ swzA;
            const uint32_t swB = (uint32_t)((ks * 2 + lB_c) * 16) ^ swzB;

            uint32_t ah[2][4], al[2][4];
#pragma unroll
            for (int mi = 0; mi < 2; mi++) {
                ldsm4(ah[mi], stg + rowA[mi] + swA);
                ldsm4(al[mi], stg + AL_OFF + rowA[mi] + swA);
            }
            uint32_t bh0[4], bh1[4], bl0[4], bl1[4];
            ldsm4(bh0, stg + BH_OFF + rowB[0] + swB);
            ldsm4(bh1, stg + BH_OFF + rowB[1] + swB);
            ldsm4(bl0, stg + BL_OFF + rowB[0] + swB);
            ldsm4(bl1, stg + BL_OFF + rowB[1] + swB);

            // last smem read of this stage happens at ks==1: release early
            if (ks == 1 && lane == 0) MBARRIER_ARRIVE(s_empt + s * 8);

            const uint32_t* bhp[4] = {bh0, bh0 + 2, bh1, bh1 + 2};
            const uint32_t* blp[4] = {bl0, bl0 + 2, bl1, bl1 + 2};

            // hh, hl, lh — mi-inner for accumulator reuse distance
#pragma unroll
            for (int ni = 0; ni < 4; ni++)
#pragma unroll
                for (int mi = 0; mi < 2; mi++) mma16816(acc[mi][ni], ah[mi], bhp[ni]);
#pragma unroll
            for (int ni = 0; ni < 4; ni++)
#pragma unroll
                for (int mi = 0; mi < 2; mi++) mma16816(acc[mi][ni], ah[mi], blp[ni]);
#pragma unroll
            for (int ni = 0; ni < 4; ni++)
#pragma unroll
                for (int mi = 0; mi < 2; mi++) mma16816(acc[mi][ni], al[mi], bhp[ni]);
        }

        // producer: refill stage s with chunk c+3 once all 8 warps released it
        if (c + 3 < NCHUNK) {
            if (tid == 0) {
                MBARRIER_WAIT_PARITY(s_empt + s * 8, par);
                const uint32_t bar = s_full + s * 8;
                MBARRIER_EXPECT_TX(bar, 24576);
                CP_BULK(stg,          Asrc + (size_t)(c + 3) * CHUNK_B, 16384, bar);
                CP_BULK(stg + BH_OFF, Wsrc + (size_t)(c + 3) * CHUNK_B, 4096, bar);
                CP_BULK(stg + BL_OFF, Wsrc + (size_t)(c + 3) * CHUNK_B + PLANE_B, 4096, bar);
            }
        }
    }

    // ---------- epilogue ----------
    const int colq = (lane & 3) * 2;
#pragma unroll
    for (int ni = 0; ni < 4; ni++) {
        const int col = ntile * 64 + nw + ni * 8 + colq;
        const float2 b2 = *(const float2*)(bias + col);
        const int2   f2 = *(const int2*)(fid + col);
        const float2 m2 = *(const float2*)(mcap + col);
        const int oc = col >> 5;
        const int oq = (col >> 3) & 3;
        const int ob = (col & 7) * 2;
#pragma unroll
        for (int mi = 0; mi < 2; mi++) {
#pragma unroll
            for (int h = 0; h < 2; h++) {
                const int row = mtile * 128 + mw + mi * 16 + (lane >> 2) + h * 8;
                const float r0 = act_clip(acc[mi][ni][h * 2 + 0] + b2.x, f2.x, m2.x);
                const float r1 = act_clip(acc[mi][ni][h * 2 + 1] + b2.y, f2.y, m2.y);
                if (OUT_FP32) {
                    *(float2*)(OutF + (size_t)row * 128 + col) = make_float2(r0, r1);
                } else {
                    const int rr = row & 127;
                    char* base = Oblk + (size_t)(row >> 7) * TILE_B + (size_t)oc * CHUNK_B;
                    const uint32_t off = blk_off(rr, oq) + ob;
                    const float h0 = __half2float(__float2half_rn(r0));
                    const float h1 = __half2float(__float2half_rn(r1));
                    *(uint32_t*)(base + off)           = pack_h2(r0, r1);
                    *(uint32_t*)(base + PLANE_B + off) = pack_h2(r0 - h0, r1 - h1);
                }
            }
        }
    }
}

// ============================================================
extern "C" void kernel_launch(void* const* d_in, const int* in_sizes, int n_in,
                              void* d_out, int out_size)
{
    const float* input  = (const float*)d_in[0];
    const float* W_in   = (const float*)d_in[1];
    const float* b_in   = (const float*)d_in[2];
    const float* W_h    = (const float*)d_in[3];
    const float* b_h    = (const float*)d_in[4];
    const float* W_out  = (const float*)d_in[5];
    const float* b_out  = (const float*)d_in[6];
    const float* m_in   = (const float*)d_in[7];
    const float* m_h    = (const float*)d_in[8];
    const float* m_out  = (const float*)d_in[9];
    const int*   fid_in  = (const int*)d_in[10];
    const int*   fid_h   = (const int*)d_in[11];
    const int*   fid_out = (const int*)d_in[12];
    float* out = (float*)d_out;

    char *ablk0, *ablk1, *wblk;
    cudaGetSymbolAddress((void**)&ablk0, g_ablk0);
    cudaGetSymbolAddress((void**)&ablk1, g_ablk1);
    cudaGetSymbolAddress((void**)&wblk, g_wblk);

    constexpr int SMEM = 128 + 3 * 24576;   // 73856 -> 3 CTAs/SM
    cudaFuncSetAttribute(bnn_gemm_kernel<false>,
                         cudaFuncAttributeMaxDynamicSharedMemorySize, SMEM);
    cudaFuncSetAttribute(bnn_gemm_kernel<true>,
                         cudaFuncAttributeMaxDynamicSharedMemorySize, SMEM);

    const int B = BATCH, X = XDIM;
    char* w_in_blk  = wblk;
    char* w_h_blk   = wblk + (size_t)4 * TILE_B;
    char* w_out_blk = wblk + (size_t)20 * TILE_B;

    const int total_slots = (B + 512 + 2048 + 128) * 64;
    split_all_kernel<<<(total_slots + 255) / 256, 256>>>(
        input, W_in, W_h, W_out, ablk0, wblk);

    dim3 blk(256);
    dim3 grid512(8, B / 128);          // 8 x 64-col tiles
    dim3 grid128(2, B / 128);          // 2 x 64-col tiles

    bnn_gemm_kernel<false><<<grid512, blk, SMEM>>>(
        ablk0, w_in_blk, b_in, fid_in, m_in, nullptr, ablk1);

    char *cur = ablk1, *nxt = ablk0;
    for (int i = 0; i < 4; i++) {
        bnn_gemm_kernel<false><<<grid512, blk, SMEM>>>(
            cur, w_h_blk + (size_t)i * 4 * TILE_B,
            b_h + i * X, fid_h + i * X, m_h + i * X, nullptr, nxt);
        char* t = cur; cur = nxt; nxt = t;
    }

    bnn_gemm_kernel<true><<<grid128, blk, SMEM>>>(
        cur, w_out_blk, b_out, fid_out, m_out, out, nullptr);
}